// round 3
// baseline (speedup 1.0000x reference)
#include <cuda_runtime.h>

typedef unsigned long long u64;

#define TPB 256
#define PXB (TPB * 2)   // 512 pixels per block, 2 per thread via f32x2

__device__ __forceinline__ u64 pk2(float lo, float hi) {
    u64 r; asm("mov.b64 %0, {%1, %2};" : "=l"(r) : "f"(lo), "f"(hi)); return r;
}
__device__ __forceinline__ void unpk(u64 v, float& lo, float& hi) {
    asm("mov.b64 {%0, %1}, %2;" : "=f"(lo), "=f"(hi) : "l"(v));
}
__device__ __forceinline__ u64 ffma2(u64 a, u64 b, u64 c) {
    u64 d; asm("fma.rn.f32x2 %0, %1, %2, %3;" : "=l"(d) : "l"(a), "l"(b), "l"(c)); return d;
}
__device__ __forceinline__ u64 fmul2(u64 a, u64 b) {
    u64 d; asm("mul.rn.f32x2 %0, %1, %2;" : "=l"(d) : "l"(a), "l"(b)); return d;
}
__device__ __forceinline__ u64 fadd2(u64 a, u64 b) {
    u64 d; asm("add.rn.f32x2 %0, %1, %2;" : "=l"(d) : "l"(a), "l"(b)); return d;
}
__device__ __forceinline__ float sin_ap(float x){ float r; asm("sin.approx.f32 %0, %1;" : "=f"(r) : "f"(x)); return r; }
__device__ __forceinline__ float ex2_ap(float x){ float r; asm("ex2.approx.f32 %0, %1;" : "=f"(r) : "f"(x)); return r; }
__device__ __forceinline__ float tanh_ap(float x){ float r; asm("tanh.approx.f32 %0, %1;" : "=f"(r) : "f"(x)); return r; }

// vector LDS.128 of two duplicated weight pairs
__device__ __forceinline__ void lds2(const u64* p, u64& a, u64& b) {
    ulonglong2 v = *(const ulonglong2*)p;
    a = v.x; b = v.y;
}

__global__ __launch_bounds__(TPB, 3) void cppn_kernel(
    const float* __restrict__ x, const float* __restrict__ y, const float* __restrict__ rr,
    const float* __restrict__ z,
    const float* __restrict__ W0, const float* __restrict__ b0,
    const float* __restrict__ Wm, const float* __restrict__ bm,
    const float* __restrict__ Wo, const float* __restrict__ bo,
    const int* __restrict__ masks_raw,
    float* __restrict__ outp, long long n)
{
    // W0 padded to 12 u64 per row so every row is 16B-aligned for LDS.128
    __shared__ alignas(16) u64 sW0[96];
    __shared__ alignas(16) u64 sB0[8];
    __shared__ alignas(16) u64 sWm[64];
    __shared__ alignas(16) u64 sBm[8];
    __shared__ alignas(16) u64 sWo[24];
    __shared__ alignas(16) u64 sBo[4];
    __shared__ u64 sFidPack;   // 24 function-ids x 2 bits

    const int tid = threadIdx.x;

    // ---- per-block constant prep (parallel) ----
    if (tid < 96) {
        int j = tid / 12, k = tid % 12;
        float w = (k < 11) ? W0[j*11 + k] * (k < 8 ? 0.1f : 1.0f) : 0.0f; // fold z/Z_SCALE; pad=0
        sW0[tid] = pk2(w, w);
    } else if (tid < 104) { float w = b0[tid-96];  sB0[tid-96]  = pk2(w, w); }
    else if (tid < 168)   { float w = Wm[tid-104]; sWm[tid-104] = pk2(w, w); }
    else if (tid < 176)   { float w = bm[tid-168]; sBm[tid-168] = pk2(w, w); }
    else if (tid < 200)   { float w = Wo[tid-176]; sWo[tid-176] = pk2(w, w); }
    else if (tid < 203)   { float w = bo[tid-200]; sBo[tid-200] = pk2(w, w); }
    else if (tid == 255) {
        // Parse masks: dtype may be int32 (JAX x64 off) or int64. Detect via
        // "layer 0's 8 entries must be a permutation of 0..7".
        int v[24];
        bool ok32 = true;
        unsigned m = 0;
        #pragma unroll
        for (int i = 0; i < 24; i++) v[i] = masks_raw[i];
        #pragma unroll
        for (int i = 0; i < 8; i++) {
            if ((unsigned)v[i] > 7u) ok32 = false; else m |= 1u << v[i];
        }
        if (!ok32 || m != 0xFFu) {
            const long long* m64 = (const long long*)masks_raw;
            #pragma unroll
            for (int i = 0; i < 24; i++) v[i] = (int)m64[i];
        }
        u64 pack = 0ull;
        #pragma unroll
        for (int l = 0; l < 3; l++)
            #pragma unroll
            for (int f = 0; f < 4; f++)
                #pragma unroll
                for (int i = 0; i < 2; i++) {
                    int unit = v[l*8 + f*2 + i];
                    pack |= ((u64)f) << (2 * (l*8 + unit));
                }
        sFidPack = pack;
    }
    __syncthreads();

    const u64 cgau   = pk2(-0.72134752044448f, -0.72134752044448f);   // -0.5*log2(e)
    const u64 cisq   = pk2(0.3989422804014327f, 0.3989422804014327f); // 1/sqrt(2pi)
    const u64 chalf  = pk2(0.5f, 0.5f);
    const u64 fidPack = sFidPack;

    const long long p = (long long)blockIdx.x * PXB + (long long)tid * 2;
    const bool ok = (p + 2 <= n);

    u64 out[8];

    { // ---- input load + first linear (W0) ----
        u64 inp[11];
        if (ok) {
            const float4* zp = (const float4*)(z + p * 8);
            float4 za0 = zp[0], za1 = zp[1], zb0 = zp[2], zb1 = zp[3];
            float2 xv = *(const float2*)(x  + p);
            float2 yv = *(const float2*)(y  + p);
            float2 rv = *(const float2*)(rr + p);
            inp[0]  = pk2(za0.x, zb0.x);
            inp[1]  = pk2(za0.y, zb0.y);
            inp[2]  = pk2(za0.z, zb0.z);
            inp[3]  = pk2(za0.w, zb0.w);
            inp[4]  = pk2(za1.x, zb1.x);
            inp[5]  = pk2(za1.y, zb1.y);
            inp[6]  = pk2(za1.z, zb1.z);
            inp[7]  = pk2(za1.w, zb1.w);
            inp[8]  = pk2(xv.x, xv.y);
            inp[9]  = pk2(yv.x, yv.y);
            inp[10] = pk2(rv.x, rv.y);
        } else {
            #pragma unroll
            for (int k = 0; k < 11; k++) inp[k] = 0ull;
        }
        #pragma unroll
        for (int j = 0; j < 8; j++) {
            u64 a = sB0[j];
            #pragma unroll
            for (int kk = 0; kk < 5; kk++) {   // k = 0..9 via LDS.128 pairs
                u64 w0v, w1v;
                lds2(&sW0[j*12 + kk*2], w0v, w1v);
                a = ffma2(inp[kk*2],     w0v, a);
                a = ffma2(inp[kk*2 + 1], w1v, a);
            }
            a = ffma2(inp[10], sW0[j*12 + 10], a);
            out[j] = a;
        }
    }

    // ---- 3 residual layers; per-unit activation chosen by uniform branch ----
    #pragma unroll
    for (int l = 0; l < 3; l++) {
        u64 pre[8];
        #pragma unroll
        for (int j = 0; j < 8; j++) {
            u64 a = sBm[j];
            #pragma unroll
            for (int kk = 0; kk < 4; kk++) {   // 8 weights via 4x LDS.128
                u64 w0v, w1v;
                lds2(&sWm[j*8 + kk*2], w0v, w1v);
                a = ffma2(out[kk*2],     w0v, a);
                a = ffma2(out[kk*2 + 1], w1v, a);
            }
            pre[j] = a;
        }
        #pragma unroll
        for (int j = 0; j < 8; j++) {
            int fid = (int)((fidPack >> (2 * (l*8 + j))) & 3ull);
            u64 t = pre[j];
            u64 nv;
            if (fid == 0) {
                float ta, tb; unpk(t, ta, tb);
                nv = pk2(sin_ap(ta), sin_ap(tb));
            } else if (fid == 1) {
                u64 arg = fmul2(fmul2(t, t), cgau);
                float g0, g1; unpk(arg, g0, g1);
                nv = fmul2(pk2(ex2_ap(g0), ex2_ap(g1)), cisq);
            } else if (fid == 2) {
                float ta, tb; unpk(t, ta, tb);
                nv = pk2(tanh_ap(ta), tanh_ap(tb));
            } else {
                nv = t;
            }
            out[j] = fmul2(fadd2(nv, out[j]), chalf);
        }
    }

    // ---- output linear + sigmoid (via tanh) + store ----
    if (ok) {
        float res[6];
        #pragma unroll
        for (int o = 0; o < 3; o++) {
            u64 a = sBo[o];
            #pragma unroll
            for (int kk = 0; kk < 4; kk++) {
                u64 w0v, w1v;
                lds2(&sWo[o*8 + kk*2], w0v, w1v);
                a = ffma2(out[kk*2],     w0v, a);
                a = ffma2(out[kk*2 + 1], w1v, a);
            }
            float ua, ub; unpk(a, ua, ub);
            res[o]     = fmaf(tanh_ap(0.5f * ua), 0.5f, 0.5f);
            res[3 + o] = fmaf(tanh_ap(0.5f * ub), 0.5f, 0.5f);
        }
        float2* op = (float2*)(outp + p * 3);
        op[0] = make_float2(res[0], res[1]);
        op[1] = make_float2(res[2], res[3]);
        op[2] = make_float2(res[4], res[5]);
    }
}

extern "C" void kernel_launch(void* const* d_in, const int* in_sizes, int n_in,
                              void* d_out, int out_size) {
    const float* x  = (const float*)d_in[0];
    const float* y  = (const float*)d_in[1];
    const float* r  = (const float*)d_in[2];
    const float* z  = (const float*)d_in[3];
    const float* W0 = (const float*)d_in[4];
    const float* b0 = (const float*)d_in[5];
    const float* Wm = (const float*)d_in[6];
    const float* bm = (const float*)d_in[7];
    const float* Wo = (const float*)d_in[8];
    const float* bo = (const float*)d_in[9];
    const int* masks = (const int*)d_in[10];

    long long n = (long long)in_sizes[0];
    int blocks = (int)((n + PXB - 1) / PXB);
    cppn_kernel<<<blocks, TPB>>>(x, y, r, z, W0, b0, Wm, bm, Wo, bo, masks,
                                 (float*)d_out, n);
}

// round 6
// speedup vs baseline: 2.3135x; 2.3135x over previous
#include <cuda_runtime.h>

typedef unsigned long long u64;

#define TPB 256
#define PXB (TPB * 2)   // 512 pixels per block, 2 per thread via f32x2

// constant layout: [0..87] W0(8x11, z-scale folded), [88..95] b0,
// [96..159] Wm, [160..167] bm, [168..191] Wo, [192..194] bo, [195] fidpack
__constant__ u64 cW[196];
__device__ u64 g_prep[196];

__device__ __forceinline__ u64 pk2(float lo, float hi) {
    u64 r; asm("mov.b64 %0, {%1, %2};" : "=l"(r) : "f"(lo), "f"(hi)); return r;
}
__device__ __forceinline__ void unpk(u64 v, float& lo, float& hi) {
    asm("mov.b64 {%0, %1}, %2;" : "=f"(lo), "=f"(hi) : "l"(v));
}
__device__ __forceinline__ u64 ffma2(u64 a, u64 b, u64 c) {
    u64 d; asm("fma.rn.f32x2 %0, %1, %2, %3;" : "=l"(d) : "l"(a), "l"(b), "l"(c)); return d;
}
__device__ __forceinline__ u64 fmul2(u64 a, u64 b) {
    u64 d; asm("mul.rn.f32x2 %0, %1, %2;" : "=l"(d) : "l"(a), "l"(b)); return d;
}
__device__ __forceinline__ u64 fadd2(u64 a, u64 b) {
    u64 d; asm("add.rn.f32x2 %0, %1, %2;" : "=l"(d) : "l"(a), "l"(b)); return d;
}
__device__ __forceinline__ float sin_ap(float x){ float r; asm("sin.approx.f32 %0, %1;" : "=f"(r) : "f"(x)); return r; }
__device__ __forceinline__ float ex2_ap(float x){ float r; asm("ex2.approx.f32 %0, %1;" : "=f"(r) : "f"(x)); return r; }
__device__ __forceinline__ float tanh_ap(float x){ float r; asm("tanh.approx.f32 %0, %1;" : "=f"(r) : "f"(x)); return r; }

// ---- prep kernel: build duplicated weight pairs + fid pack in device scratch ----
__global__ void prep_kernel(
    const float* __restrict__ W0, const float* __restrict__ b0,
    const float* __restrict__ Wm, const float* __restrict__ bm,
    const float* __restrict__ Wo, const float* __restrict__ bo,
    const int* __restrict__ masks_raw)
{
    const int tid = threadIdx.x;
    if (tid < 88) {
        int k = tid % 11;
        float w = W0[tid] * (k < 8 ? 0.1f : 1.0f);   // fold z / Z_SCALE
        g_prep[tid] = pk2(w, w);
    } else if (tid < 96)  { float w = b0[tid-88];  g_prep[tid] = pk2(w, w); }
    else if (tid < 160)   { float w = Wm[tid-96];  g_prep[tid] = pk2(w, w); }
    else if (tid < 168)   { float w = bm[tid-160]; g_prep[tid] = pk2(w, w); }
    else if (tid < 192)   { float w = Wo[tid-168]; g_prep[tid] = pk2(w, w); }
    else if (tid < 195)   { float w = bo[tid-192]; g_prep[tid] = pk2(w, w); }
    else if (tid == 255) {
        // Parse masks: dtype may be int32 (JAX x64 off) or int64. Detect via
        // "layer 0's 8 entries must be a permutation of 0..7".
        int v[24];
        bool ok32 = true;
        unsigned m = 0;
        #pragma unroll
        for (int i = 0; i < 24; i++) v[i] = masks_raw[i];
        #pragma unroll
        for (int i = 0; i < 8; i++) {
            if ((unsigned)v[i] > 7u) ok32 = false; else m |= 1u << v[i];
        }
        if (!ok32 || m != 0xFFu) {
            const long long* m64 = (const long long*)masks_raw;
            #pragma unroll
            for (int i = 0; i < 24; i++) v[i] = (int)m64[i];
        }
        u64 pack = 0ull;
        #pragma unroll
        for (int l = 0; l < 3; l++)
            #pragma unroll
            for (int f = 0; f < 4; f++)
                #pragma unroll
                for (int i = 0; i < 2; i++) {
                    int unit = v[l*8 + f*2 + i];
                    pack |= ((u64)f) << (2 * (l*8 + unit));
                }
        g_prep[195] = pack;
    }
}

__global__ __launch_bounds__(TPB, 3) void cppn_kernel(
    const float* __restrict__ x, const float* __restrict__ y, const float* __restrict__ rr,
    const float* __restrict__ z,
    float* __restrict__ outp, long long n)
{
    const int tid = threadIdx.x;

    const u64 cgau   = pk2(-0.72134752044448f, -0.72134752044448f);   // -0.5*log2(e)
    const u64 cisq   = pk2(0.3989422804014327f, 0.3989422804014327f); // 1/sqrt(2pi)
    const u64 chalf  = pk2(0.5f, 0.5f);
    const u64 fidPack = cW[195];

    const long long p = (long long)blockIdx.x * PXB + (long long)tid * 2;
    const bool ok = (p + 2 <= n);

    u64 out[8];

    { // ---- input load + first linear (W0) ----
        u64 inp[11];
        if (ok) {
            const float4* zp = (const float4*)(z + p * 8);
            float4 za0 = zp[0], za1 = zp[1], zb0 = zp[2], zb1 = zp[3];
            float2 xv = *(const float2*)(x  + p);
            float2 yv = *(const float2*)(y  + p);
            float2 rv = *(const float2*)(rr + p);
            inp[0]  = pk2(za0.x, zb0.x);
            inp[1]  = pk2(za0.y, zb0.y);
            inp[2]  = pk2(za0.z, zb0.z);
            inp[3]  = pk2(za0.w, zb0.w);
            inp[4]  = pk2(za1.x, zb1.x);
            inp[5]  = pk2(za1.y, zb1.y);
            inp[6]  = pk2(za1.z, zb1.z);
            inp[7]  = pk2(za1.w, zb1.w);
            inp[8]  = pk2(xv.x, xv.y);
            inp[9]  = pk2(yv.x, yv.y);
            inp[10] = pk2(rv.x, rv.y);
        } else {
            #pragma unroll
            for (int k = 0; k < 11; k++) inp[k] = 0ull;
        }
        #pragma unroll
        for (int j = 0; j < 8; j++) {
            u64 a = cW[88 + j];
            #pragma unroll
            for (int k = 0; k < 11; k++) a = ffma2(inp[k], cW[j*11 + k], a);
            out[j] = a;
        }
    }

    // ---- 3 residual layers; per-unit activation chosen by uniform branch ----
    #pragma unroll
    for (int l = 0; l < 3; l++) {
        u64 pre[8];
        #pragma unroll
        for (int j = 0; j < 8; j++) {
            u64 a = cW[160 + j];
            #pragma unroll
            for (int k = 0; k < 8; k++) a = ffma2(out[k], cW[96 + j*8 + k], a);
            pre[j] = a;
        }
        #pragma unroll
        for (int j = 0; j < 8; j++) {
            int fid = (int)((fidPack >> (2 * (l*8 + j))) & 3ull);
            u64 t = pre[j];
            u64 nv;
            if (fid == 0) {
                float ta, tb; unpk(t, ta, tb);
                nv = pk2(sin_ap(ta), sin_ap(tb));
            } else if (fid == 1) {
                u64 arg = fmul2(fmul2(t, t), cgau);
                float g0, g1; unpk(arg, g0, g1);
                nv = fmul2(pk2(ex2_ap(g0), ex2_ap(g1)), cisq);
            } else if (fid == 2) {
                float ta, tb; unpk(t, ta, tb);
                nv = pk2(tanh_ap(ta), tanh_ap(tb));
            } else {
                nv = t;
            }
            out[j] = fmul2(fadd2(nv, out[j]), chalf);
        }
    }

    // ---- output linear + sigmoid (via tanh) + store ----
    if (ok) {
        float res[6];
        #pragma unroll
        for (int o = 0; o < 3; o++) {
            u64 a = cW[192 + o];
            #pragma unroll
            for (int k = 0; k < 8; k++) a = ffma2(out[k], cW[168 + o*8 + k], a);
            float ua, ub; unpk(a, ua, ub);
            res[o]     = fmaf(tanh_ap(0.5f * ua), 0.5f, 0.5f);
            res[3 + o] = fmaf(tanh_ap(0.5f * ub), 0.5f, 0.5f);
        }
        float2* op = (float2*)(outp + p * 3);
        op[0] = make_float2(res[0], res[1]);
        op[1] = make_float2(res[2], res[3]);
        op[2] = make_float2(res[4], res[5]);
    }
}

extern "C" void kernel_launch(void* const* d_in, const int* in_sizes, int n_in,
                              void* d_out, int out_size) {
    const float* x  = (const float*)d_in[0];
    const float* y  = (const float*)d_in[1];
    const float* r  = (const float*)d_in[2];
    const float* z  = (const float*)d_in[3];
    const float* W0 = (const float*)d_in[4];
    const float* b0 = (const float*)d_in[5];
    const float* Wm = (const float*)d_in[6];
    const float* bm = (const float*)d_in[7];
    const float* Wo = (const float*)d_in[8];
    const float* bo = (const float*)d_in[9];
    const int* masks = (const int*)d_in[10];

    long long n = (long long)in_sizes[0];

    prep_kernel<<<1, TPB>>>(W0, b0, Wm, bm, Wo, bo, masks);

    // Resolve the REAL device address of g_prep (the symbol name in host code
    // is only a shadow — passing it directly made the D2D memcpy fail).
    void* src = 0;
    cudaGetSymbolAddress(&src, g_prep);
    cudaMemcpyToSymbolAsync(cW, src, 196 * sizeof(u64), 0,
                            cudaMemcpyDeviceToDevice, 0);

    int blocks = (int)((n + PXB - 1) / PXB);
    cppn_kernel<<<blocks, TPB>>>(x, y, r, z, (float*)d_out, n);
}